// round 9
// baseline (speedup 1.0000x reference)
#include <cuda_runtime.h>
#include <cstdint>
#include <math.h>

#define NB 8
#define NN 2048
#define DD 128
#define ALPHA 0.2f
#define PPAD 68

// ------------------------- device scratch ----------------------------------
__device__ __align__(16) unsigned short g_WhT_hi[NB * DD * NN];  // [b][d][j] bf16 hi
__device__ __align__(16) unsigned short g_WhT_lo[NB * DD * NN];  // [b][d][j] bf16 lo
__device__ __align__(16) float4 g_row4[NB * NN];  // (es, exp(es), exp(.2es), 0)
__device__ __align__(16) float4 g_col4[NB * NN];  // (ed, exp(ed), exp(.2ed), 0)

// ------------------------- helpers -----------------------------------------
__device__ __forceinline__ uint32_t smem_u32(const void* p) {
    uint32_t a;
    asm("{ .reg .u64 t; cvta.to.shared.u64 t, %1; cvt.u32.u64 %0, t; }" : "=r"(a) : "l"(p));
    return a;
}
#define SW128(o) ((o) ^ (((o) >> 3) & 0x70))

__device__ __forceinline__ void ldm_x4(uint32_t* r, uint32_t addr) {
    asm volatile("ldmatrix.sync.aligned.m8n8.x4.shared.b16 {%0,%1,%2,%3}, [%4];"
                 : "=r"(r[0]), "=r"(r[1]), "=r"(r[2]), "=r"(r[3]) : "r"(addr));
}
__device__ __forceinline__ void mma_bf16(float* c, const uint32_t* a, const uint32_t* b) {
    asm volatile("mma.sync.aligned.m16n8k16.row.col.f32.bf16.bf16.f32 "
                 "{%0,%1,%2,%3}, {%4,%5,%6,%7}, {%8,%9}, {%0,%1,%2,%3};"
                 : "+f"(c[0]), "+f"(c[1]), "+f"(c[2]), "+f"(c[3])
                 : "r"(a[0]), "r"(a[1]), "r"(a[2]), "r"(a[3]), "r"(b[0]), "r"(b[1]));
}

#define CP_ASYNC16(dst, src) \
    asm volatile("cp.async.cg.shared.global [%0], [%1], 16;" :: "r"(dst), "l"(src) : "memory")
#define CP_COMMIT()  asm volatile("cp.async.commit_group;" ::: "memory")
#define CP_WAIT0()   asm volatile("cp.async.wait_group 0;" ::: "memory")

// ---- f32x2 helpers ---------------------------------------------------------
__device__ __forceinline__ void ffma2(unsigned long long& acc,
                                      unsigned long long a, unsigned long long b) {
    asm("fma.rn.f32x2 %0, %1, %2, %0;" : "+l"(acc) : "l"(a), "l"(b));
}
__device__ __forceinline__ unsigned long long pack2(float x, float y) {
    unsigned long long r;
    asm("mov.b64 %0, {%1, %2};" : "=l"(r) : "f"(x), "f"(y));
    return r;
}
__device__ __forceinline__ void unpack2(float& lo, float& hi, unsigned long long v) {
    asm("mov.b64 {%0, %1}, %2;" : "=f"(lo), "=f"(hi) : "l"(v));
}

// ---------------------------------------------------------------------------
// Kernel A: Wh = h @ W (FFMA2 GEMM, 64 rows/block), fused:
//   - bf16 hi/lo split of Wh^T -> g_WhT_hi/lo [b][d][j]
//   - g_row4/g_col4 factorized exp tables
// ---------------------------------------------------------------------------
#define SMEM_A (128*128*4 + 128*PPAD*4)

__global__ __launch_bounds__(256) void wh_gemm_kernel(
    const float* __restrict__ h, const float* __restrict__ W,
    const float* __restrict__ a_src, const float* __restrict__ a_dst)
{
    extern __shared__ __align__(16) char smem_raw[];
    float* Ws = (float*)smem_raw;               // [k][d] 128x128
    float* hs = Ws + 128 * 128;                 // [k][row] 128xPPAD

    int t = threadIdx.x;
    int r0blk = blockIdx.x * 64;

    {
        const float4* src = (const float4*)W;
        float4* dst = (float4*)Ws;
#pragma unroll
        for (int q = 0; q < 16; ++q) dst[t + q * 256] = src[t + q * 256];
    }
#pragma unroll
    for (int q = 0; q < 32; ++q) {
        int idx = t + q * 256;
        int k = idx & 127, row = idx >> 7;
        hs[k * PPAD + row] = h[(size_t)(r0blk + row) * DD + k];
    }
    __syncthreads();

    int tx = t & 15, ty = t >> 4;
    int d0 = tx * 8;

    unsigned long long acc[4][4];
#pragma unroll
    for (int r = 0; r < 4; ++r)
#pragma unroll
        for (int c = 0; c < 4; ++c) acc[r][c] = 0ull;

#pragma unroll 4
    for (int k = 0; k < 128; ++k) {
        float4 hv = *(const float4*)&hs[k * PPAD + ty * 4];
        ulonglong2 w0 = *(const ulonglong2*)&Ws[k * 128 + d0];
        ulonglong2 w1 = *(const ulonglong2*)&Ws[k * 128 + d0 + 4];
        unsigned long long pp[4];
        pp[0] = pack2(hv.x, hv.x); pp[1] = pack2(hv.y, hv.y);
        pp[2] = pack2(hv.z, hv.z); pp[3] = pack2(hv.w, hv.w);
#pragma unroll
        for (int r = 0; r < 4; ++r) {
            ffma2(acc[r][0], pp[r], w0.x);
            ffma2(acc[r][1], pp[r], w0.y);
            ffma2(acc[r][2], pp[r], w1.x);
            ffma2(acc[r][3], pp[r], w1.y);
        }
    }

    float asv[8], adv[8];
    {
        float4 s0 = *(const float4*)&a_src[d0];
        float4 s1 = *(const float4*)&a_src[d0 + 4];
        float4 t0 = *(const float4*)&a_dst[d0];
        float4 t1 = *(const float4*)&a_dst[d0 + 4];
        asv[0]=s0.x; asv[1]=s0.y; asv[2]=s0.z; asv[3]=s0.w;
        asv[4]=s1.x; asv[5]=s1.y; asv[6]=s1.z; asv[7]=s1.w;
        adv[0]=t0.x; adv[1]=t0.y; adv[2]=t0.z; adv[3]=t0.w;
        adv[4]=t1.x; adv[5]=t1.y; adv[6]=t1.z; adv[7]=t1.w;
    }

#pragma unroll
    for (int r = 0; r < 4; ++r) {
        int row = r0blk + ty * 4 + r;
        float w[8];
        unpack2(w[0], w[1], acc[r][0]); unpack2(w[2], w[3], acc[r][1]);
        unpack2(w[4], w[5], acc[r][2]); unpack2(w[6], w[7], acc[r][3]);
        float sa = 0.f, sd = 0.f;
#pragma unroll
        for (int c = 0; c < 8; ++c) { sa = fmaf(w[c], asv[c], sa); sd = fmaf(w[c], adv[c], sd); }
#pragma unroll
        for (int off = 8; off > 0; off >>= 1) {
            sa += __shfl_xor_sync(0xffffffffu, sa, off);
            sd += __shfl_xor_sync(0xffffffffu, sd, off);
        }
        if (tx == 0) {
            g_row4[row] = make_float4(sa, __expf(sa), __expf(ALPHA * sa), 0.f);
            g_col4[row] = make_float4(sd, __expf(sd), __expf(ALPHA * sd), 0.f);
        }
    }

    // ---- transpose + bf16 split staging (reuse hs region) ----
    __syncthreads();
    unsigned short* sthi = (unsigned short*)hs;          // [128 d][64 j]
    unsigned short* stlo = sthi + 128 * 64;
#pragma unroll
    for (int r = 0; r < 4; ++r) {
        float w[8];
        unpack2(w[0], w[1], acc[r][0]); unpack2(w[2], w[3], acc[r][1]);
        unpack2(w[4], w[5], acc[r][2]); unpack2(w[6], w[7], acc[r][3]);
        int jl = ty * 4 + r;
#pragma unroll
        for (int c = 0; c < 8; ++c) {
            uint32_t u = __float_as_uint(w[c]);
            float hf = __uint_as_float(u & 0xffff0000u);
            float lo = w[c] - hf;
            sthi[(d0 + c) * 64 + jl] = (unsigned short)(u >> 16);
            stlo[(d0 + c) * 64 + jl] = (unsigned short)(__float_as_uint(lo) >> 16);
        }
    }
    __syncthreads();

    int b = r0blk >> 11;
    int jblk = r0blk & (NN - 1);
    const uint4* s4h = (const uint4*)sthi;
    const uint4* s4l = (const uint4*)stlo;
    uint4* gh = (uint4*)g_WhT_hi;
    uint4* gl = (uint4*)g_WhT_lo;
#pragma unroll
    for (int q = 0; q < 4; ++q) {
        int idx = t + 256 * q;
        int d = idx >> 3, ch = idx & 7;
        size_t dst = (size_t)(b * DD + d) * 256 + (jblk >> 3) + ch;
        gh[dst] = s4h[idx];
        gl[dst] = s4l[idx];
    }
}

// ---------------------------------------------------------------------------
// Kernel B: pipelined HMMA bf16x3 aggregation, d-split for occupancy.
//  Grid (2 d-halves, 16 i-tiles, 8 b), 256 threads, 2 blocks/SM.
//  Block tile 128 i x 64 d; warp tile 32 i x 32 d (wy=wid&3, wx=wid>>2).
//  P hi/lo double-buffered (64KB), V hi/lo double-buffered (32KB).
// ---------------------------------------------------------------------------
#define SM_P    0            // + buf*32768 : Phi at +0, Plo at +16384
#define SM_V    65536        // + buf*16384 : Vhi at +0, Vlo at +8192
#define SM_L    98304        // 128 floats
#define SMEM_B_TOTAL 98816

__global__ __launch_bounds__(256, 2) void attn_mma_kernel(
    const int* __restrict__ adj, float* __restrict__ out)
{
    extern __shared__ __align__(1024) char sm[];
    uint32_t smb = smem_u32(sm);
    int t = threadIdx.x, wid = t >> 5, lane = t & 31;
    int dh = blockIdx.x;               // d-half: 0 or 1
    int i0 = blockIdx.y * 128;
    int b  = blockIdx.z;
    int wy = wid & 3, wx = wid >> 2;

    int i = t >> 1, half = t & 1;      // fillP: row i, j-half (32 j each)
    float4 rv = g_row4[b * NN + i0 + i];
    float esi = rv.x, Ai = rv.y, Ci = rv.z;
    const int* __restrict__ adjrow = adj + (size_t)(i0 + i) * NN;
    const float4* __restrict__ col4 = g_col4 + b * NN;
    const uint4* vhi_g = (const uint4*)g_WhT_hi + ((size_t)b * DD + dh * 64) * 256;
    const uint4* vlo_g = (const uint4*)g_WhT_lo + ((size_t)b * DD + dh * 64) * 256;
    float lsum = 0.f;

    float acc[2][4][4];
#pragma unroll
    for (int m = 0; m < 2; ++m)
#pragma unroll
        for (int n = 0; n < 4; ++n)
#pragma unroll
            for (int q = 0; q < 4; ++q) acc[m][n][q] = 0.f;

    int grp = lane >> 3, lrow = lane & 7;

    // ---- pipeline helpers ----
    auto loadV = [&](int c, int buf) {
        uint32_t vbase = smb + SM_V + buf * 16384;
        int j8 = (c * 64) >> 3;
#pragma unroll
        for (int q = 0; q < 2; ++q) {
            int idx = t + 256 * q;              // 0..511
            int d = idx >> 3, ch = idx & 7;     // d 0..63
            uint32_t off = SW128((uint32_t)(d * 128 + ch * 16));
            CP_ASYNC16(vbase + off,        (const char*)(vhi_g + d * 256 + j8 + ch));
            CP_ASYNC16(vbase + 8192 + off, (const char*)(vlo_g + d * 256 + j8 + ch));
        }
    };
    auto loadAdj = [&](int c, int4* am) {
        const int4* arow4 = (const int4*)(adjrow + c * 64 + half * 32);
#pragma unroll
        for (int u = 0; u < 8; ++u) am[u] = __ldg(arow4 + u);
    };
    auto fillP = [&](int c, int buf, const int4* am) {
        int j0 = c * 64;
        char* ph_base = sm + SM_P + buf * 32768;
        char* pl_base = ph_base + 16384;
#pragma unroll
        for (int g4 = 0; g4 < 4; ++g4) {        // 8 j per group
            uint32_t hw[4], lw[4];
#pragma unroll
            for (int pr = 0; pr < 4; ++pr) {
                int jj = g4 * 8 + pr * 2;       // local 0..31
                int jg = j0 + half * 32 + jj;
                int a0, a1;
                {
                    int4 av = am[jj >> 2];
                    if ((jj & 3) == 0) { a0 = av.x; a1 = av.y; }
                    else               { a0 = av.z; a1 = av.w; }
                }
                float4 c0 = __ldg(&col4[jg]);
                float4 c1 = __ldg(&col4[jg + 1]);
                float s0 = esi + c0.x;
                float s1 = esi + c1.x;
                float v0 = (s0 > 0.f) ? Ai * c0.y : Ci * c0.z;
                float v1 = (s1 > 0.f) ? Ai * c1.y : Ci * c1.z;
                float p0 = (a0 > 0) ? v0 : 0.f;
                float p1 = (a1 > 0) ? v1 : 0.f;
                lsum += p0 + p1;
                uint32_t u0 = __float_as_uint(p0);
                uint32_t u1 = __float_as_uint(p1);
                float l0 = p0 - __uint_as_float(u0 & 0xffff0000u);
                float l1 = p1 - __uint_as_float(u1 & 0xffff0000u);
                hw[pr] = __byte_perm(u0, u1, 0x7632);
                lw[pr] = __byte_perm(__float_as_uint(l0), __float_as_uint(l1), 0x7632);
            }
            uint32_t off = SW128((uint32_t)(i * 128 + half * 64 + g4 * 16));
            *(uint4*)(ph_base + off) = make_uint4(hw[0], hw[1], hw[2], hw[3]);
            *(uint4*)(pl_base + off) = make_uint4(lw[0], lw[1], lw[2], lw[3]);
        }
    };

    // ---- prologue: fill buffer 0 ----
    int4 am[8];
    loadV(0, 0); CP_COMMIT();
    loadAdj(0, am);
    fillP(0, 0, am);
    CP_WAIT0();
    __syncthreads();

    // ---- main pipelined loop ----
    for (int c = 0; c < 32; ++c) {
        int cb = c & 1, nb = cb ^ 1;

        if (c < 31) {
            loadV(c + 1, nb); CP_COMMIT();
            loadAdj(c + 1, am);
        }

        // MMA on buffer cb
        {
            uint32_t phb = smb + SM_P + cb * 32768;
            uint32_t plb = phb + 16384;
            uint32_t vhb = smb + SM_V + cb * 16384;
            uint32_t vlb = vhb + 8192;
#pragma unroll
            for (int ks = 0; ks < 4; ++ks) {
                uint32_t ah[2][4], al[2][4];
#pragma unroll
                for (int mt = 0; mt < 2; ++mt) {
                    int arow = wy * 32 + mt * 16 + (grp & 1) * 8 + lrow;
                    uint32_t aoff = SW128((uint32_t)(arow * 128 + ks * 32 + (grp >> 1) * 16));
                    ldm_x4(ah[mt], phb + aoff);
                    ldm_x4(al[mt], plb + aoff);
                }
#pragma unroll
                for (int np = 0; np < 2; ++np) {
                    int brow = wx * 32 + np * 16 + (grp >> 1) * 8 + lrow;
                    uint32_t boff = SW128((uint32_t)(brow * 128 + ks * 32 + (grp & 1) * 16));
                    uint32_t bh[4], bl[4];
                    ldm_x4(bh, vhb + boff);
                    ldm_x4(bl, vlb + boff);
#pragma unroll
                    for (int mt = 0; mt < 2; ++mt) {
                        mma_bf16(acc[mt][np * 2],     ah[mt], bh);
                        mma_bf16(acc[mt][np * 2 + 1], ah[mt], bh + 2);
                        mma_bf16(acc[mt][np * 2],     ah[mt], bl);
                        mma_bf16(acc[mt][np * 2 + 1], ah[mt], bl + 2);
                        mma_bf16(acc[mt][np * 2],     al[mt], bh);
                        mma_bf16(acc[mt][np * 2 + 1], al[mt], bh + 2);
                    }
                }
            }
        }

        if (c < 31) fillP(c + 1, nb, am);
        CP_WAIT0();
        __syncthreads();
    }

    // ---- row sums -> smem (2 threads per row) ----
    {
        float other = __shfl_xor_sync(0xffffffffu, lsum, 1);
        if (half == 0) ((float*)(sm + SM_L))[i] = lsum + other;
    }
    __syncthreads();

    // ---- epilogue: scale frags by 1/l and store (this block's d-half) ----
    const float* Ls = (const float*)(sm + SM_L);
#pragma unroll
    for (int mt = 0; mt < 2; ++mt) {
        int r0 = wy * 32 + mt * 16 + (lane >> 2);
        float inv0 = 1.f / Ls[r0];
        float inv1 = 1.f / Ls[r0 + 8];
        float* orow0 = out + ((size_t)(b * NN) + i0 + r0) * DD + dh * 64 + wx * 32 + 2 * (lane & 3);
        float* orow1 = orow0 + 8 * DD;
#pragma unroll
        for (int nt = 0; nt < 4; ++nt) {
            float2 v0; v0.x = acc[mt][nt][0] * inv0; v0.y = acc[mt][nt][1] * inv0;
            float2 v1; v1.x = acc[mt][nt][2] * inv1; v1.y = acc[mt][nt][3] * inv1;
            *(float2*)(orow0 + nt * 8) = v0;
            *(float2*)(orow1 + nt * 8) = v1;
        }
    }
}

// ---------------------------------------------------------------------------
extern "C" void kernel_launch(void* const* d_in, const int* in_sizes, int n_in,
                              void* d_out, int out_size)
{
    const float* h     = (const float*)d_in[0];
    const int*   adj   = (const int*)d_in[1];
    const float* W     = (const float*)d_in[2];
    const float* a_src = (const float*)d_in[3];
    const float* a_dst = (const float*)d_in[4];
    float* out = (float*)d_out;

    cudaFuncSetAttribute(wh_gemm_kernel,  cudaFuncAttributeMaxDynamicSharedMemorySize, SMEM_A);
    cudaFuncSetAttribute(attn_mma_kernel, cudaFuncAttributeMaxDynamicSharedMemorySize, SMEM_B_TOTAL);

    wh_gemm_kernel<<<NB * NN / 64, 256, SMEM_A>>>(h, W, a_src, a_dst);
    attn_mma_kernel<<<dim3(2, NN / 128, NB), 256, SMEM_B_TOTAL>>>(adj, out);
}

// round 10
// speedup vs baseline: 1.9625x; 1.9625x over previous
#include <cuda_runtime.h>
#include <cuda_fp16.h>
#include <cstdint>
#include <math.h>

#define NB 8
#define NN 2048
#define DD 128
#define ALPHA 0.2f
#define PPAD 68

// ------------------------- device scratch ----------------------------------
__device__ __align__(16) unsigned short g_WhT_hi[NB * DD * NN];  // [b][d][j] fp16 hi
__device__ __align__(16) unsigned short g_WhT_lo[NB * DD * NN];  // [b][d][j] fp16 lo
__device__ __align__(16) float4 g_row4[NB * NN];  // (es, exp(es), exp(.2es), 0)
__device__ __align__(16) float4 g_col4[NB * NN];  // (ed, exp(ed), exp(.2ed), 0)

// ------------------------- helpers -----------------------------------------
__device__ __forceinline__ uint32_t smem_u32(const void* p) {
    uint32_t a;
    asm("{ .reg .u64 t; cvta.to.shared.u64 t, %1; cvt.u32.u64 %0, t; }" : "=r"(a) : "l"(p));
    return a;
}
#define SW128(o) ((o) ^ (((o) >> 3) & 0x70))

__device__ __forceinline__ void ldm_x4(uint32_t* r, uint32_t addr) {
    asm volatile("ldmatrix.sync.aligned.m8n8.x4.shared.b16 {%0,%1,%2,%3}, [%4];"
                 : "=r"(r[0]), "=r"(r[1]), "=r"(r[2]), "=r"(r[3]) : "r"(addr));
}
__device__ __forceinline__ void mma_f16(float* c, const uint32_t* a, const uint32_t* b) {
    asm volatile("mma.sync.aligned.m16n8k16.row.col.f32.f16.f16.f32 "
                 "{%0,%1,%2,%3}, {%4,%5,%6,%7}, {%8,%9}, {%0,%1,%2,%3};"
                 : "+f"(c[0]), "+f"(c[1]), "+f"(c[2]), "+f"(c[3])
                 : "r"(a[0]), "r"(a[1]), "r"(a[2]), "r"(a[3]), "r"(b[0]), "r"(b[1]));
}

#define CP_ASYNC16(dst, src) \
    asm volatile("cp.async.cg.shared.global [%0], [%1], 16;" :: "r"(dst), "l"(src) : "memory")
#define CP_COMMIT()  asm volatile("cp.async.commit_group;" ::: "memory")
#define CP_WAIT0()   asm volatile("cp.async.wait_group 0;" ::: "memory")

// ---- f32x2 helpers ---------------------------------------------------------
__device__ __forceinline__ void ffma2(unsigned long long& acc,
                                      unsigned long long a, unsigned long long b) {
    asm("fma.rn.f32x2 %0, %1, %2, %0;" : "+l"(acc) : "l"(a), "l"(b));
}
__device__ __forceinline__ unsigned long long pack2(float x, float y) {
    unsigned long long r;
    asm("mov.b64 %0, {%1, %2};" : "=l"(r) : "f"(x), "f"(y));
    return r;
}
__device__ __forceinline__ void unpack2(float& lo, float& hi, unsigned long long v) {
    asm("mov.b64 {%0, %1}, %2;" : "=f"(lo), "=f"(hi) : "l"(v));
}

// ---------------------------------------------------------------------------
// Kernel A: Wh = h @ W (FFMA2 GEMM, 64 rows/block), fused:
//   - fp16 hi/lo split of Wh^T -> g_WhT_hi/lo [b][d][j]
//   - g_row4/g_col4 factorized exp tables
// ---------------------------------------------------------------------------
#define SMEM_A (128*128*4 + 128*PPAD*4)

__global__ __launch_bounds__(256) void wh_gemm_kernel(
    const float* __restrict__ h, const float* __restrict__ W,
    const float* __restrict__ a_src, const float* __restrict__ a_dst)
{
    extern __shared__ __align__(16) char smem_raw[];
    float* Ws = (float*)smem_raw;               // [k][d] 128x128
    float* hs = Ws + 128 * 128;                 // [k][row] 128xPPAD

    int t = threadIdx.x;
    int r0blk = blockIdx.x * 64;

    {
        const float4* src = (const float4*)W;
        float4* dst = (float4*)Ws;
#pragma unroll
        for (int q = 0; q < 16; ++q) dst[t + q * 256] = src[t + q * 256];
    }
#pragma unroll
    for (int q = 0; q < 32; ++q) {
        int idx = t + q * 256;
        int k = idx & 127, row = idx >> 7;
        hs[k * PPAD + row] = h[(size_t)(r0blk + row) * DD + k];
    }
    __syncthreads();

    int tx = t & 15, ty = t >> 4;
    int d0 = tx * 8;

    unsigned long long acc[4][4];
#pragma unroll
    for (int r = 0; r < 4; ++r)
#pragma unroll
        for (int c = 0; c < 4; ++c) acc[r][c] = 0ull;

#pragma unroll 4
    for (int k = 0; k < 128; ++k) {
        float4 hv = *(const float4*)&hs[k * PPAD + ty * 4];
        ulonglong2 w0 = *(const ulonglong2*)&Ws[k * 128 + d0];
        ulonglong2 w1 = *(const ulonglong2*)&Ws[k * 128 + d0 + 4];
        unsigned long long pp[4];
        pp[0] = pack2(hv.x, hv.x); pp[1] = pack2(hv.y, hv.y);
        pp[2] = pack2(hv.z, hv.z); pp[3] = pack2(hv.w, hv.w);
#pragma unroll
        for (int r = 0; r < 4; ++r) {
            ffma2(acc[r][0], pp[r], w0.x);
            ffma2(acc[r][1], pp[r], w0.y);
            ffma2(acc[r][2], pp[r], w1.x);
            ffma2(acc[r][3], pp[r], w1.y);
        }
    }

    float asv[8], adv[8];
    {
        float4 s0 = *(const float4*)&a_src[d0];
        float4 s1 = *(const float4*)&a_src[d0 + 4];
        float4 t0 = *(const float4*)&a_dst[d0];
        float4 t1 = *(const float4*)&a_dst[d0 + 4];
        asv[0]=s0.x; asv[1]=s0.y; asv[2]=s0.z; asv[3]=s0.w;
        asv[4]=s1.x; asv[5]=s1.y; asv[6]=s1.z; asv[7]=s1.w;
        adv[0]=t0.x; adv[1]=t0.y; adv[2]=t0.z; adv[3]=t0.w;
        adv[4]=t1.x; adv[5]=t1.y; adv[6]=t1.z; adv[7]=t1.w;
    }

#pragma unroll
    for (int r = 0; r < 4; ++r) {
        int row = r0blk + ty * 4 + r;
        float w[8];
        unpack2(w[0], w[1], acc[r][0]); unpack2(w[2], w[3], acc[r][1]);
        unpack2(w[4], w[5], acc[r][2]); unpack2(w[6], w[7], acc[r][3]);
        float sa = 0.f, sd = 0.f;
#pragma unroll
        for (int c = 0; c < 8; ++c) { sa = fmaf(w[c], asv[c], sa); sd = fmaf(w[c], adv[c], sd); }
#pragma unroll
        for (int off = 8; off > 0; off >>= 1) {
            sa += __shfl_xor_sync(0xffffffffu, sa, off);
            sd += __shfl_xor_sync(0xffffffffu, sd, off);
        }
        if (tx == 0) {
            g_row4[row] = make_float4(sa, __expf(sa), __expf(ALPHA * sa), 0.f);
            g_col4[row] = make_float4(sd, __expf(sd), __expf(ALPHA * sd), 0.f);
        }
    }

    // ---- transpose + fp16 hi/lo split staging (reuse hs region) ----
    __syncthreads();
    unsigned short* sthi = (unsigned short*)hs;          // [128 d][64 j]
    unsigned short* stlo = sthi + 128 * 64;
#pragma unroll
    for (int r = 0; r < 4; ++r) {
        float w[8];
        unpack2(w[0], w[1], acc[r][0]); unpack2(w[2], w[3], acc[r][1]);
        unpack2(w[4], w[5], acc[r][2]); unpack2(w[6], w[7], acc[r][3]);
        int jl = ty * 4 + r;
#pragma unroll
        for (int c = 0; c < 8; ++c) {
            __half hv = __float2half_rn(w[c]);
            float hf = __half2float(hv);
            __half lv = __float2half_rn(w[c] - hf);
            sthi[(d0 + c) * 64 + jl] = __half_as_ushort(hv);
            stlo[(d0 + c) * 64 + jl] = __half_as_ushort(lv);
        }
    }
    __syncthreads();

    int b = r0blk >> 11;
    int jblk = r0blk & (NN - 1);
    const uint4* s4h = (const uint4*)sthi;
    const uint4* s4l = (const uint4*)stlo;
    uint4* gh = (uint4*)g_WhT_hi;
    uint4* gl = (uint4*)g_WhT_lo;
#pragma unroll
    for (int q = 0; q < 4; ++q) {
        int idx = t + 256 * q;
        int d = idx >> 3, ch = idx & 7;
        size_t dst = (size_t)(b * DD + d) * 256 + (jblk >> 3) + ch;
        gh[dst] = s4h[idx];
        gl[dst] = s4l[idx];
    }
}

// ---------------------------------------------------------------------------
// Kernel B: pipelined HMMA fp16x2 aggregation. Grid (16, 8), 256 threads.
//  Block tile 128 i x 128 d; warp tile 64 i x 32 d (wy=wid&1, wx=wid>>1).
//  P fp16 (single, no split) double-buffered; V hi/lo fp16 double-buffered.
//  out = P*Vhi + P*Vlo (A-frags shared between the two GEMMs).
// ---------------------------------------------------------------------------
#define SM_COL4 0            // 32768 B
#define SM_P    32768        // + buf*16384
#define SM_V    65536        // + buf*32768 : Vhi at +0, Vlo at +16384
#define SM_L    131072       // 128 floats
#define SMEM_B_TOTAL 131584

__global__ __launch_bounds__(256) void attn_mma_kernel(
    const int* __restrict__ adj, float* __restrict__ out)
{
    extern __shared__ __align__(1024) char sm[];
    uint32_t smb = smem_u32(sm);
    int t = threadIdx.x, wid = t >> 5, lane = t & 31;
    int b = blockIdx.y;
    int i0 = blockIdx.x * 128;
    int wy = wid & 1, wx = wid >> 1;

    // col factor table for this batch
    {
        const float4* src = g_col4 + b * NN;
        float4* dst = (float4*)(sm + SM_COL4);
#pragma unroll
        for (int q = 0; q < 8; ++q) dst[t + 256 * q] = src[t + 256 * q];
    }

    int i = t >> 1, half = t & 1;      // fillP: row i, j-half (32 j each)
    float4 rv = g_row4[b * NN + i0 + i];
    float esi = rv.x, Ai = rv.y, Ci = rv.z;
    const int* __restrict__ adjrow = adj + (size_t)(i0 + i) * NN;
    const float4* col4 = (const float4*)(sm + SM_COL4);
    const uint4* vhi_g = (const uint4*)g_WhT_hi + (size_t)b * DD * 256;
    const uint4* vlo_g = (const uint4*)g_WhT_lo + (size_t)b * DD * 256;
    float lsum = 0.f;

    __syncthreads();   // col4 ready

    float acc[4][4][4];
#pragma unroll
    for (int m = 0; m < 4; ++m)
#pragma unroll
        for (int n = 0; n < 4; ++n)
#pragma unroll
            for (int q = 0; q < 4; ++q) acc[m][n][q] = 0.f;

    int grp = lane >> 3, lrow = lane & 7;

    // ---- pipeline helpers ----
    auto loadV = [&](int c, int buf) {
        uint32_t vbase = smb + SM_V + buf * 32768;
        int j8 = (c * 64) >> 3;
#pragma unroll
        for (int q = 0; q < 4; ++q) {
            int idx = t + 256 * q;              // 0..1023
            int d = idx >> 3, ch = idx & 7;     // d 0..127
            uint32_t off = SW128((uint32_t)(d * 128 + ch * 16));
            CP_ASYNC16(vbase + off,         (const char*)(vhi_g + d * 256 + j8 + ch));
            CP_ASYNC16(vbase + 16384 + off, (const char*)(vlo_g + d * 256 + j8 + ch));
        }
    };
    auto loadAdj = [&](int c, int4* am) {
        const int4* arow4 = (const int4*)(adjrow + c * 64 + half * 32);
#pragma unroll
        for (int u = 0; u < 8; ++u) am[u] = __ldg(arow4 + u);
    };
    auto fillP = [&](int c, int buf, const int4* am) {
        int j0 = c * 64;
        char* ph_base = sm + SM_P + buf * 16384;
#pragma unroll
        for (int g4 = 0; g4 < 4; ++g4) {        // 8 j per group
            uint32_t hw[4];
#pragma unroll
            for (int pr = 0; pr < 4; ++pr) {
                int jj = g4 * 8 + pr * 2;       // local 0..31
                int jg = j0 + half * 32 + jj;
                int a0, a1;
                {
                    int4 av = am[jj >> 2];
                    if ((jj & 3) == 0) { a0 = av.x; a1 = av.y; }
                    else               { a0 = av.z; a1 = av.w; }
                }
                float4 c0 = col4[jg];
                float4 c1 = col4[jg + 1];
                float s0 = esi + c0.x;
                float s1 = esi + c1.x;
                float v0 = (s0 > 0.f) ? Ai * c0.y : Ci * c0.z;
                float v1 = (s1 > 0.f) ? Ai * c1.y : Ci * c1.z;
                float p0 = (a0 > 0) ? v0 : 0.f;
                float p1 = (a1 > 0) ? v1 : 0.f;
                lsum += p0 + p1;
                __half2 hh = __floats2half2_rn(p0, p1);  // p0 -> low half (j even)
                hw[pr] = *reinterpret_cast<uint32_t*>(&hh);
            }
            uint32_t off = SW128((uint32_t)(i * 128 + half * 64 + g4 * 16));
            *(uint4*)(ph_base + off) = make_uint4(hw[0], hw[1], hw[2], hw[3]);
        }
    };

    // ---- prologue: fill buffer 0 ----
    int4 am[8];
    loadV(0, 0); CP_COMMIT();
    loadAdj(0, am);
    fillP(0, 0, am);
    CP_WAIT0();
    __syncthreads();

    // ---- main pipelined loop ----
    for (int c = 0; c < 32; ++c) {
        int cb = c & 1, nb = cb ^ 1;

        if (c < 31) {
            loadV(c + 1, nb); CP_COMMIT();
            loadAdj(c + 1, am);
        }

        // MMA on buffer cb
        {
            uint32_t phb = smb + SM_P + cb * 16384;
            uint32_t vhb = smb + SM_V + cb * 32768;
            uint32_t vlb = vhb + 16384;
#pragma unroll
            for (int ks = 0; ks < 4; ++ks) {
                uint32_t ah[4][4];
#pragma unroll
                for (int mt = 0; mt < 4; ++mt) {
                    int arow = wy * 64 + mt * 16 + (grp & 1) * 8 + lrow;
                    uint32_t aoff = SW128((uint32_t)(arow * 128 + ks * 32 + (grp >> 1) * 16));
                    ldm_x4(ah[mt], phb + aoff);
                }
#pragma unroll
                for (int np = 0; np < 2; ++np) {
                    int brow = wx * 32 + np * 16 + (grp >> 1) * 8 + lrow;
                    uint32_t boff = SW128((uint32_t)(brow * 128 + ks * 32 + (grp & 1) * 16));
                    uint32_t bh[4], bl[4];
                    ldm_x4(bh, vhb + boff);
                    ldm_x4(bl, vlb + boff);
#pragma unroll
                    for (int mt = 0; mt < 4; ++mt) {
                        mma_f16(acc[mt][np * 2],     ah[mt], bh);
                        mma_f16(acc[mt][np * 2 + 1], ah[mt], bh + 2);
                        mma_f16(acc[mt][np * 2],     ah[mt], bl);
                        mma_f16(acc[mt][np * 2 + 1], ah[mt], bl + 2);
                    }
                }
            }
        }

        if (c < 31) fillP(c + 1, nb, am);
        CP_WAIT0();
        __syncthreads();
    }

    // ---- row sums -> smem (2 threads per row) ----
    {
        float other = __shfl_xor_sync(0xffffffffu, lsum, 1);
        if (half == 0) ((float*)(sm + SM_L))[i] = lsum + other;
    }
    __syncthreads();

    // ---- epilogue: scale frags by 1/l and store ----
    const float* Ls = (const float*)(sm + SM_L);
#pragma unroll
    for (int mt = 0; mt < 4; ++mt) {
        int r0 = wy * 64 + mt * 16 + (lane >> 2);
        float inv0 = 1.f / Ls[r0];
        float inv1 = 1.f / Ls[r0 + 8];
        float* orow0 = out + ((size_t)(b * NN) + i0 + r0) * DD + wx * 32 + 2 * (lane & 3);
        float* orow1 = orow0 + 8 * DD;
#pragma unroll
        for (int nt = 0; nt < 4; ++nt) {
            float2 v0; v0.x = acc[mt][nt][0] * inv0; v0.y = acc[mt][nt][1] * inv0;
            float2 v1; v1.x = acc[mt][nt][2] * inv1; v1.y = acc[mt][nt][3] * inv1;
            *(float2*)(orow0 + nt * 8) = v0;
            *(float2*)(orow1 + nt * 8) = v1;
        }
    }
}

// ---------------------------------------------------------------------------
extern "C" void kernel_launch(void* const* d_in, const int* in_sizes, int n_in,
                              void* d_out, int out_size)
{
    const float* h     = (const float*)d_in[0];
    const int*   adj   = (const int*)d_in[1];
    const float* W     = (const float*)d_in[2];
    const float* a_src = (const float*)d_in[3];
    const float* a_dst = (const float*)d_in[4];
    float* out = (float*)d_out;

    cudaFuncSetAttribute(wh_gemm_kernel,  cudaFuncAttributeMaxDynamicSharedMemorySize, SMEM_A);
    cudaFuncSetAttribute(attn_mma_kernel, cudaFuncAttributeMaxDynamicSharedMemorySize, SMEM_B_TOTAL);

    wh_gemm_kernel<<<NB * NN / 64, 256, SMEM_A>>>(h, W, a_src, a_dst);
    attn_mma_kernel<<<dim3(NN / 128, NB), 256, SMEM_B_TOTAL>>>(adj, out);
}